// round 2
// baseline (speedup 1.0000x reference)
#include <cuda_runtime.h>
#include <cstdint>

// Problem constants (fixed shapes)
#define BB 16
#define NNODES 1024
#define DD 64
#define CC 64
#define KK 20
#define NODES (BB * NNODES)   // 16384

// ---------------- device scratch (no allocs allowed) ----------------
__device__ float g_P[NODES * CC];     // feats @ Wp (folded)          4 MB
__device__ float g_Q[NODES * CC];     // feats @ Wq + bq (folded)     4 MB
__device__ float g_f0[NODES];         // feats[:, :, 0] packed
__device__ int   g_nn[NODES * KK];    // knn indices (set; order irrelevant)
__device__ float g_Wq[DD * CC];
__device__ float g_Wp[DD * CC];
__device__ float g_bq[CC];
__device__ float g_W2[CC * CC];
__device__ float g_b2[CC];

// ---------------- kernel 0: fold BN into weights ----------------
__global__ void fold_kernel(const float* __restrict__ w1, const float* __restrict__ b1,
                            const float* __restrict__ g1, const float* __restrict__ be1,
                            const float* __restrict__ mu1, const float* __restrict__ v1,
                            const float* __restrict__ w2, const float* __restrict__ b2,
                            const float* __restrict__ g2, const float* __restrict__ be2,
                            const float* __restrict__ mu2, const float* __restrict__ v2)
{
    int t = threadIdx.x;
    for (int i = t; i < DD * CC; i += 256) {
        int c = i & 63;
        float s = g1[c] * rsqrtf(v1[c] + 1e-3f);
        float wa = w1[i];              // w1[d][c], d in [0,64)
        float wb = w1[DD * CC + i];    // w1[64+d][c]
        g_Wq[i] = (wa - wb) * s;       // center part: (w1a - w1b)
        g_Wp[i] = wb * s;              // neighbor part
    }
    for (int i = t; i < CC * CC; i += 256) {
        int c = i & 63;
        float s = g2[c] * rsqrtf(v2[c] + 1e-3f);
        g_W2[i] = w2[i] * s;
    }
    if (t < CC) {
        float s1 = g1[t] * rsqrtf(v1[t] + 1e-3f);
        g_bq[t] = (b1[t] - mu1[t]) * s1 + be1[t];
        float s2 = g2[t] * rsqrtf(v2[t] + 1e-3f);
        g_b2[t] = (b2[t] - mu2[t]) * s2 + be2[t];
    }
}

// ---------------- kernel 1: P,Q = feats @ {Wp, Wq}  (+ pack f0) ----------------
__global__ __launch_bounds__(256) void pq_kernel(const float* __restrict__ feats)
{
    __shared__ float sf[32 * 64];
    int t = threadIdx.x;
    int rowbase = blockIdx.x * 32;
    const float* src = feats + (size_t)rowbase * 64;
#pragma unroll
    for (int j = 0; j < 8; ++j) sf[t + j * 256] = src[t + j * 256];
    __syncthreads();
    if (t < 32) g_f0[rowbase + t] = sf[t * 64];

    int c  = t & 63;
    int rg = t >> 6;   // 0..3, each owns 8 rows
    float accp[8], accq[8];
#pragma unroll
    for (int q = 0; q < 8; ++q) { accp[q] = 0.f; accq[q] = 0.f; }
#pragma unroll 8
    for (int d = 0; d < 64; ++d) {
        float wp = g_Wp[d * 64 + c];
        float wq = g_Wq[d * 64 + c];
#pragma unroll
        for (int q = 0; q < 8; ++q) {
            float f = sf[(rg * 8 + q) * 64 + d];
            accp[q] = fmaf(f, wp, accp[q]);
            accq[q] = fmaf(f, wq, accq[q]);
        }
    }
    float bq = g_bq[c];
#pragma unroll
    for (int q = 0; q < 8; ++q) {
        int row = rowbase + rg * 8 + q;
        g_P[row * 64 + c] = accp[q];
        g_Q[row * 64 + c] = accq[q] + bq;
    }
}

// ---------------- kernel 2: per-row top-20-smallest via radix select ----------------
__global__ __launch_bounds__(256) void topk_kernel(const float* __restrict__ adj)
{
    __shared__ unsigned skey[1024];
    __shared__ int hist[256];
    __shared__ unsigned s_prefix;
    __shared__ int s_want, s_cntLess, s_cntEq;
    __shared__ int sSel[KK];
    __shared__ int sEq[32];

    int t = threadIdx.x;
    int row = blockIdx.x;
    int b = row >> 10;
    const float fi = g_f0[row];
    const float* arow = adj + (size_t)row * 1024;
    const float* f0b = g_f0 + b * 1024;

#pragma unroll
    for (int jj = 0; jj < 4; ++jj) {
        int j = t + jj * 256;
        float a = arow[j] * fabsf(f0b[j] - fi);   // a >= 0 -> float bits are uint-ordered
        skey[j] = __float_as_uint(a);
    }
    if (t == 0) { s_prefix = 0u; s_want = KK; s_cntLess = 0; s_cntEq = 0; }
    __syncthreads();

#pragma unroll
    for (int shift = 24; shift >= 0; shift -= 8) {
        hist[t] = 0;
        __syncthreads();
        unsigned long long pfx = (unsigned long long)s_prefix;
        int lane = t & 31;
#pragma unroll
        for (int jj = 0; jj < 4; ++jj) {
            unsigned key = skey[t + jj * 256];
            bool cand = ((((unsigned long long)key) >> (shift + 8)) == pfx);
            unsigned bal = __ballot_sync(0xffffffffu, cand);
            if (cand) {
                int bucket = (key >> shift) & 255;
                unsigned grp = __match_any_sync(bal, bucket);
                int leader = __ffs(grp) - 1;
                if (lane == leader) atomicAdd(&hist[bucket], __popc(grp));
            }
        }
        __syncthreads();
        if (t < 32) {  // warp 0: parallel scan over 256 bins
            int h[8]; int tot = 0;
#pragma unroll
            for (int q = 0; q < 8; ++q) { h[q] = hist[t * 8 + q]; tot += h[q]; }
            int inc = tot;
#pragma unroll
            for (int off = 1; off < 32; off <<= 1) {
                int v = __shfl_up_sync(0xffffffffu, inc, off);
                if (t >= off) inc += v;
            }
            int excl = inc - tot;
            int want = s_want;
            if (want > excl && want <= inc) {      // exactly one lane
                int run = excl; int bsel = 0;
#pragma unroll
                for (int q = 0; q < 8; ++q) {
                    run += h[q];
                    if (run >= want) { bsel = q; want -= (run - h[q]); break; }
                }
                s_prefix = (s_prefix << 8) | (unsigned)(t * 8 + bsel);
                s_want = want;
            }
        }
        __syncthreads();
    }

    unsigned T = s_prefix;  // exact key of the 20th smallest
#pragma unroll
    for (int jj = 0; jj < 4; ++jj) {
        int j = t + jj * 256;
        unsigned key = skey[j];
        if (key < T) {
            int p = atomicAdd(&s_cntLess, 1);   // guaranteed < 20
            sSel[p] = j;
        } else if (key == T) {
            int p = atomicAdd(&s_cntEq, 1);
            if (p < 32) sEq[p] = j;
        }
    }
    __syncthreads();
    if (t == 0) {
        int nl = s_cntLess;
        int rem = KK - nl;
        int m = s_cntEq; if (m > 32) m = 32;
        for (int r = 0; r < rem; ++r) {          // lowest indices among ties (matches lax.top_k)
            int best = 0x7fffffff, bi = -1;
            for (int q = 0; q < m; ++q)
                if (sEq[q] < best) { best = sEq[q]; bi = q; }
            if (bi >= 0) { sSel[nl + r] = best; sEq[bi] = 0x7fffffff; }
            else         { sSel[nl + r] = row & 1023; }  // unreachable safety
        }
    }
    __syncthreads();
    if (t < KK) g_nn[row * KK + t] = sSel[t];
}

// ---------------- kernel 3: fused gather + x1 + GEMM2 + mean ----------------
// 8 nodes/block = 160 (n,k)-rows. x1 staged in smem; GEMM2 via packed fma.rn.f32x2.
#define SXLD 68   // row pitch (floats): 16B-aligned, bank-conflict-free column reads

__global__ __launch_bounds__(256, 2) void edge_kernel(float* __restrict__ out)
{
    extern __shared__ float sm[];
    float* sX   = sm;                     // 160 * 68
    float* sW   = sX + 160 * SXLD;        // 64 * 64
    float* sB2  = sW + 4096;              // 64
    float* sOutP = sB2 + 64;              // 4 * 512 deterministic partials
    int*   sJ   = (int*)(sOutP + 4 * 512);// 160 gathered P-row indices

    int t = threadIdx.x;
    int n0 = blockIdx.x * 8;

    for (int i = t; i < 4096; i += 256) sW[i] = g_W2[i];
    if (t < 64) sB2[t] = g_b2[t];
    for (int i = t; i < 4 * 512; i += 256) sOutP[i] = 0.f;
    if (t < 160) {
        int g = n0 + t / 20;
        int b = g >> 10;
        sJ[t] = (b << 10) + g_nn[g * KK + (t % 20)];
    }
    __syncthreads();

    // phase 1: x1[r][e] = relu(Q[node] + P[nn]) -> smem, coalesced float4
#pragma unroll
    for (int it = 0; it < 10; ++it) {
        int tau = t + it * 256;
        int r = tau >> 4;
        int e4 = tau & 15;
        int g = n0 + r / 20;
        float4 p4 = *(const float4*)(g_P + (size_t)sJ[r] * 64 + e4 * 4);
        float4 q4 = *(const float4*)(g_Q + (size_t)g * 64 + e4 * 4);
        float4 x;
        x.x = fmaxf(p4.x + q4.x, 0.f);
        x.y = fmaxf(p4.y + q4.y, 0.f);
        x.z = fmaxf(p4.z + q4.z, 0.f);
        x.w = fmaxf(p4.w + q4.w, 0.f);
        *(float4*)(sX + r * SXLD + e4 * 4) = x;
    }
    __syncthreads();

    // phase 2: 160x64 @ 64x64, thread tile = 5 rows x 8 cols, packed f32x2 FMA
    int tx = t & 7;     // col group (8 cols)
    int ty = t >> 3;    // row group (5 rows; 5 | 20 so a group never straddles nodes)
    const float* xbase = sX + ty * 5 * SXLD;
    const float* wbase = sW + tx * 8;

    unsigned long long acc[5][4];
#pragma unroll
    for (int i = 0; i < 5; ++i)
#pragma unroll
        for (int p = 0; p < 4; ++p) acc[i][p] = 0ull;

#pragma unroll 4
    for (int e = 0; e < 64; ++e) {
        ulonglong2 wA = *(const ulonglong2*)(wbase + e * 64);      // cols +0..3
        ulonglong2 wB = *(const ulonglong2*)(wbase + e * 64 + 4);  // cols +4..7
#pragma unroll
        for (int i = 0; i < 5; ++i) {
            unsigned xu = __float_as_uint(xbase[i * SXLD + e]);
            unsigned long long xx;
            asm("mov.b64 %0, {%1, %1};" : "=l"(xx) : "r"(xu));
            asm("fma.rn.f32x2 %0, %1, %2, %0;" : "+l"(acc[i][0]) : "l"(xx), "l"(wA.x));
            asm("fma.rn.f32x2 %0, %1, %2, %0;" : "+l"(acc[i][1]) : "l"(xx), "l"(wA.y));
            asm("fma.rn.f32x2 %0, %1, %2, %0;" : "+l"(acc[i][2]) : "l"(xx), "l"(wB.x));
            asm("fma.rn.f32x2 %0, %1, %2, %0;" : "+l"(acc[i][3]) : "l"(xx), "l"(wB.y));
        }
    }

    // epilogue: bias + relu per row, sum 5 rows locally (all same node), store partial
    {
        int ni = ty >> 2;        // node within block
        int part = ty & 3;       // which 5-row chunk of the node's 20 rows
        float cs[8];
#pragma unroll
        for (int u = 0; u < 8; ++u) cs[u] = 0.f;
#pragma unroll
        for (int i = 0; i < 5; ++i) {
#pragma unroll
            for (int p = 0; p < 4; ++p) {
                int c0 = tx * 8 + p * 2;
                unsigned long long v = acc[i][p];
                float lo = __uint_as_float((unsigned)v);
                float hi = __uint_as_float((unsigned)(v >> 32));
                cs[p * 2]     += fmaxf(lo + sB2[c0], 0.f);
                cs[p * 2 + 1] += fmaxf(hi + sB2[c0 + 1], 0.f);
            }
        }
        float* dst = sOutP + part * 512 + ni * 64 + tx * 8;
        *(float4*)(dst)     = make_float4(cs[0], cs[1], cs[2], cs[3]);
        *(float4*)(dst + 4) = make_float4(cs[4], cs[5], cs[6], cs[7]);
    }
    __syncthreads();

    // mean over k, write out (deterministic reduction order)
    for (int i = t; i < 512; i += 256) {
        float s = sOutP[i] + sOutP[512 + i] + sOutP[1024 + i] + sOutP[1536 + i];
        out[(size_t)n0 * 64 + i] = s * (1.0f / 20.0f);
    }
}

// ---------------- launch ----------------
extern "C" void kernel_launch(void* const* d_in, const int* in_sizes, int n_in,
                              void* d_out, int out_size)
{
    (void)in_sizes; (void)n_in; (void)out_size;
    const float* feats = (const float*)d_in[0];
    const float* adj   = (const float*)d_in[1];
    const float* w1    = (const float*)d_in[2];
    const float* b1    = (const float*)d_in[3];
    const float* g1    = (const float*)d_in[4];
    const float* be1   = (const float*)d_in[5];
    const float* mu1   = (const float*)d_in[6];
    const float* v1    = (const float*)d_in[7];
    const float* w2    = (const float*)d_in[8];
    const float* b2    = (const float*)d_in[9];
    const float* g2    = (const float*)d_in[10];
    const float* be2   = (const float*)d_in[11];
    const float* mu2   = (const float*)d_in[12];
    const float* v2    = (const float*)d_in[13];
    float* out = (float*)d_out;

    const int smem_edge = (160 * SXLD + 4096 + 64 + 4 * 512) * 4 + 160 * 4;
    cudaFuncSetAttribute(edge_kernel, cudaFuncAttributeMaxDynamicSharedMemorySize, smem_edge);

    fold_kernel<<<1, 256>>>(w1, b1, g1, be1, mu1, v1, w2, b2, g2, be2, mu2, v2);
    pq_kernel<<<NODES / 32, 256>>>(feats);
    topk_kernel<<<NODES, 256>>>(adj);
    edge_kernel<<<NODES / 8, 256, smem_edge>>>(out);
}